// round 6
// baseline (speedup 1.0000x reference)
#include <cuda_runtime.h>

#define EPSV   1e-5f
#define DW_THR 4.0f
#define PW_THR 0.001f

// Shapes: B=64, C=128, O=256, H=W=56, HW=3136
__device__ float g_y[64 * 128 * 3136];   // pruned depthwise output [B,C,HW]
__device__ int   g_keep[64 * 128];       // per-(b,c) keep flag
__device__ int   g_idx[64 * 128];        // per-b compacted kept-channel list
__device__ int   g_cnt[64];              // per-b kept count

// ---------------------------------------------------------------------------
// packed fp32x2 helpers (Blackwell FFMA2)
// ---------------------------------------------------------------------------
__device__ __forceinline__ unsigned long long fma2(unsigned long long a,
                                                   unsigned long long b,
                                                   unsigned long long c) {
    unsigned long long d;
    asm("fma.rn.f32x2 %0, %1, %2, %3;" : "=l"(d) : "l"(a), "l"(b), "l"(c));
    return d;
}
__device__ __forceinline__ unsigned long long pk2(float lo, float hi) {
    unsigned long long d;
    asm("mov.b64 %0, {%1, %2};" : "=l"(d) : "f"(lo), "f"(hi));
    return d;
}
__device__ __forceinline__ float2 upk2(unsigned long long v) {
    float2 r;
    asm("mov.b64 {%0, %1}, %2;" : "=f"(r.x), "=f"(r.y) : "l"(v));
    return r;
}

// ---------------------------------------------------------------------------
// Depthwise 3x3 + bias + BN1 + ReLU + per-(b,c) prune. (unchanged — passing)
// ---------------------------------------------------------------------------
__global__ __launch_bounds__(256) void dw_kernel(
    const float* __restrict__ x,
    const float* __restrict__ dw_w, const float* __restrict__ dw_b,
    const float* __restrict__ g1,  const float* __restrict__ b1,
    const float* __restrict__ m1,  const float* __restrict__ v1)
{
    __shared__ float sx[3136];
    __shared__ float red[8];
    __shared__ float s_bmax;

    const int slice = blockIdx.x;          // b*128 + c
    const int c = slice & 127;
    const float* xs = x + (size_t)slice * 3136;

    const float w0 = dw_w[c * 9 + 0], w1 = dw_w[c * 9 + 1], w2 = dw_w[c * 9 + 2];
    const float w3 = dw_w[c * 9 + 3], w4 = dw_w[c * 9 + 4], w5 = dw_w[c * 9 + 5];
    const float w6 = dw_w[c * 9 + 6], w7 = dw_w[c * 9 + 7], w8 = dw_w[c * 9 + 8];
    const float s = g1[c] * rsqrtf(v1[c] + EPSV);
    const float t = fmaf(dw_b[c] - m1[c], s, b1[c]);

    const int tid = threadIdx.x;

    {
        const float4* x4 = (const float4*)xs;
        float4* s4 = (float4*)sx;
        for (int i = tid; i < 784; i += 256) s4[i] = x4[i];
    }
    __syncthreads();

    float lv[14];
    float mx = 0.f;
    int col = 0, band = 0;
    if (tid < 224) {
        col  = tid % 56;
        band = tid / 56;               // rows band*14 .. band*14+13
        const bool cL = (col > 0), cR = (col < 55);
        const int base = band * 14 * 56 + col;

        float r0c0 = 0.f, r0c1 = 0.f, r0c2 = 0.f;
        if (band > 0) {
            int a = base - 56;
            r0c0 = cL ? sx[a - 1] : 0.f; r0c1 = sx[a]; r0c2 = cR ? sx[a + 1] : 0.f;
        }
        float r1c0 = cL ? sx[base - 1] : 0.f;
        float r1c1 = sx[base];
        float r1c2 = cR ? sx[base + 1] : 0.f;

#pragma unroll
        for (int j = 0; j < 14; j++) {
            int rr = band * 14 + j + 1;
            float r2c0 = 0.f, r2c1 = 0.f, r2c2 = 0.f;
            if (rr < 56) {
                int a = base + (j + 1) * 56;
                r2c0 = cL ? sx[a - 1] : 0.f; r2c1 = sx[a]; r2c2 = cR ? sx[a + 1] : 0.f;
            }
            float acc =        r0c0 * w0;
            acc = fmaf(r0c1, w1, acc); acc = fmaf(r0c2, w2, acc);
            acc = fmaf(r1c0, w3, acc); acc = fmaf(r1c1, w4, acc);
            acc = fmaf(r1c2, w5, acc);
            acc = fmaf(r2c0, w6, acc); acc = fmaf(r2c1, w7, acc);
            acc = fmaf(r2c2, w8, acc);
            float z = fmaxf(fmaf(acc, s, t), 0.f);
            lv[j] = z;
            mx = fmaxf(mx, z);
            r0c0 = r1c0; r0c1 = r1c1; r0c2 = r1c2;
            r1c0 = r2c0; r1c1 = r2c1; r1c2 = r2c2;
        }
    }

    for (int off = 16; off; off >>= 1)
        mx = fmaxf(mx, __shfl_xor_sync(0xffffffffu, mx, off));
    if ((tid & 31) == 0) red[tid >> 5] = mx;
    __syncthreads();
    if (tid == 0) {
        float m = red[0];
#pragma unroll
        for (int i = 1; i < 8; i++) m = fmaxf(m, red[i]);
        s_bmax = m;
        g_keep[slice] = (m >= DW_THR) ? 1 : 0;
    }
    __syncthreads();

    if (s_bmax >= DW_THR && tid < 224) {
        float* yo = g_y + (size_t)slice * 3136 + band * 14 * 56 + col;
#pragma unroll
        for (int j = 0; j < 14; j++) yo[j * 56] = lv[j];
    }
}

// ---------------------------------------------------------------------------
// Per-batch compaction of kept channels
// ---------------------------------------------------------------------------
__global__ void compact_kernel() {
    const int b = blockIdx.x;
    const int tid = threadIdx.x;              // 128 threads
    __shared__ int wcnt[4];
    const int f = g_keep[b * 128 + tid];
    const unsigned bal = __ballot_sync(0xffffffffu, f);
    const int lane = tid & 31, w = tid >> 5;
    const int pre = __popc(bal & ((1u << lane) - 1u));
    if (lane == 0) wcnt[w] = __popc(bal);
    __syncthreads();
    int off = 0;
#pragma unroll
    for (int i = 0; i < 4; i++) if (i < w) off += wcnt[i];
    if (f) g_idx[b * 128 + off + pre] = tid;
    if (tid == 0) g_cnt[b] = wcnt[0] + wcnt[1] + wcnt[2] + wcnt[3];
}

// ---------------------------------------------------------------------------
// Pointwise conv + BN2 + ReLU + FUSED per-(b,o) prune.
// One block owns a 16-O x 3136-HW stripe: grid (16 o-tiles, 64 batches).
// Thread (tx,ty): o = ob+ty, 4 hw per iter, 49 iters. No sync in main loop.
// Max accumulates in registers across full hw; failing rows re-zeroed locally.
// ---------------------------------------------------------------------------
__global__ __launch_bounds__(256) void pw_kernel(
    const float* __restrict__ pw_w, const float* __restrict__ pw_b,
    const float* __restrict__ g2,  const float* __restrict__ b2,
    const float* __restrict__ m2,  const float* __restrict__ v2,
    float* __restrict__ out)
{
    __shared__ float sW[128 * 16];            // [k][o] for this block's 16 o's
    __shared__ const float* sptr[128];        // g_y row pointer per compacted k

    const int tid = threadIdx.x;
    const int tx = tid & 15;                  // hw: 16 threads x 4 floats
    const int ty = tid >> 4;                  // o : 16 values
    const int ob = blockIdx.x * 16;
    const int b  = blockIdx.y;

    const int cnt = g_cnt[b];

    // stage compacted indices -> row pointers, and W gather (once per block)
    if (tid < 128 && tid < cnt) {
        int ch = g_idx[b * 128 + tid];
        sptr[tid] = g_y + ((size_t)(b * 128 + ch)) * 3136;
    }
    __syncthreads();
    for (int i = tid; i < cnt * 16; i += 256) {
        int k = i >> 4, o = i & 15;
        // recompute ch from pointer-free path: gather via sptr is for Y; for W
        // we need the channel index -> re-load g_idx (L2-hot, once per block)
        int ch = g_idx[b * 128 + k];
        sW[i] = pw_w[(ob + o) * 128 + ch];
    }
    __syncthreads();

    const int o = ob + ty;
    const float sc = g2[o] * rsqrtf(v2[o] + EPSV);
    const float tt = fmaf(pw_b[o] - m2[o], sc, b2[o]);
    float* const outrow = out + ((size_t)(b * 256 + o)) * 3136;

    float m = 0.f;
    for (int it = 0; it < 49; it++) {
        const int hw = it * 64 + tx * 4;
        unsigned long long a0 = 0ull, a1 = 0ull;
        for (int k = 0; k < cnt; k++) {
            float4 yv = *(const float4*)(sptr[k] + hw);
            float a = sW[k * 16 + ty];
            unsigned long long aa = pk2(a, a);
            a0 = fma2(aa, pk2(yv.x, yv.y), a0);
            a1 = fma2(aa, pk2(yv.z, yv.w), a1);
        }
        float2 p0 = upk2(a0), p1 = upk2(a1);
        float z0 = fmaxf(fmaf(p0.x, sc, tt), 0.f);
        float z1 = fmaxf(fmaf(p0.y, sc, tt), 0.f);
        float z2 = fmaxf(fmaf(p1.x, sc, tt), 0.f);
        float z3 = fmaxf(fmaf(p1.y, sc, tt), 0.f);
        m = fmaxf(m, fmaxf(fmaxf(z0, z1), fmaxf(z2, z3)));
        *(float4*)(outrow + hw) = make_float4(z0, z1, z2, z3);
    }

    // per-o max across the 16 tx lanes (tx = low 4 bits of lane id)
#pragma unroll
    for (int off = 1; off < 16; off <<= 1)
        m = fmaxf(m, __shfl_xor_sync(0xffffffffu, m, off));

    // fused prune: the 16 threads of this o-row re-zero it (rare)
    if (m < PW_THR) {
        const float4 zz = make_float4(0.f, 0.f, 0.f, 0.f);
        for (int it = 0; it < 49; it++)
            *(float4*)(outrow + it * 64 + tx * 4) = zz;
    }
}

// ---------------------------------------------------------------------------
extern "C" void kernel_launch(void* const* d_in, const int* in_sizes, int n_in,
                              void* d_out, int out_size)
{
    const float* x    = (const float*)d_in[0];
    const float* dw_w = (const float*)d_in[1];
    const float* dw_b = (const float*)d_in[2];
    const float* g1   = (const float*)d_in[3];
    const float* b1   = (const float*)d_in[4];
    const float* m1   = (const float*)d_in[5];
    const float* v1   = (const float*)d_in[6];
    const float* pw_w = (const float*)d_in[7];
    const float* pw_b = (const float*)d_in[8];
    const float* g2   = (const float*)d_in[9];
    const float* b2   = (const float*)d_in[10];
    const float* m2   = (const float*)d_in[11];
    const float* v2   = (const float*)d_in[12];
    float* out = (float*)d_out;

    dw_kernel<<<64 * 128, 256>>>(x, dw_w, dw_b, g1, b1, m1, v1);
    compact_kernel<<<64, 128>>>();
    pw_kernel<<<dim3(16, 64), 256>>>(pw_w, pw_b, g2, b2, m2, v2, out);
}

// round 7
// speedup vs baseline: 1.2088x; 1.2088x over previous
#include <cuda_runtime.h>

#define EPSV   1e-5f
#define DW_THR 4.0f
#define PW_THR 0.001f

// Shapes: B=64, C=128, O=256, H=W=56, HW=3136
__device__ float g_y[64 * 128 * 3136];   // pruned depthwise output [B,C,HW]
__device__ int   g_keep[64 * 128];       // per-(b,c) keep flag
__device__ int   g_idx[64 * 128];        // per-b compacted kept-channel list
__device__ int   g_cnt[64];              // per-b kept count
__device__ int   g_max[64 * 256];        // per-(b,o) max(z) as int bits (z>=0)

// ---------------------------------------------------------------------------
// packed fp32x2 helpers (Blackwell FFMA2)
// ---------------------------------------------------------------------------
__device__ __forceinline__ unsigned long long fma2(unsigned long long a,
                                                   unsigned long long b,
                                                   unsigned long long c) {
    unsigned long long d;
    asm("fma.rn.f32x2 %0, %1, %2, %3;" : "=l"(d) : "l"(a), "l"(b), "l"(c));
    return d;
}
__device__ __forceinline__ unsigned long long mul2(unsigned long long a,
                                                   unsigned long long b) {
    unsigned long long d;
    asm("mul.rn.f32x2 %0, %1, %2;" : "=l"(d) : "l"(a), "l"(b));
    return d;
}
__device__ __forceinline__ unsigned long long pk2(float lo, float hi) {
    unsigned long long d;
    asm("mov.b64 %0, {%1, %2};" : "=l"(d) : "f"(lo), "f"(hi));
    return d;
}
__device__ __forceinline__ float2 upk2(unsigned long long v) {
    float2 r;
    asm("mov.b64 {%0, %1}, %2;" : "=f"(r.x), "=f"(r.y) : "l"(v));
    return r;
}

// ---------------------------------------------------------------------------
// Depthwise 3x3 + bias + BN1 + ReLU + per-(b,c) prune.
// FFMA2 column pairs: 224 threads = 28 col-pairs x 8 bands x 7 rows.
// Per-lane fp32x2 ops are bit-identical to the scalar version's FMA chain.
// ---------------------------------------------------------------------------
__global__ __launch_bounds__(256) void dw_kernel(
    const float* __restrict__ x,
    const float* __restrict__ dw_w, const float* __restrict__ dw_b,
    const float* __restrict__ g1,  const float* __restrict__ b1,
    const float* __restrict__ m1,  const float* __restrict__ v1)
{
    __shared__ float sx[3136];
    __shared__ float red[8];
    __shared__ float s_bmax;

    const int slice = blockIdx.x;          // b*128 + c
    const int c = slice & 127;
    const float* xs = x + (size_t)slice * 3136;

    const unsigned long long ww0 = pk2(dw_w[c*9+0], dw_w[c*9+0]);
    const unsigned long long ww1 = pk2(dw_w[c*9+1], dw_w[c*9+1]);
    const unsigned long long ww2 = pk2(dw_w[c*9+2], dw_w[c*9+2]);
    const unsigned long long ww3 = pk2(dw_w[c*9+3], dw_w[c*9+3]);
    const unsigned long long ww4 = pk2(dw_w[c*9+4], dw_w[c*9+4]);
    const unsigned long long ww5 = pk2(dw_w[c*9+5], dw_w[c*9+5]);
    const unsigned long long ww6 = pk2(dw_w[c*9+6], dw_w[c*9+6]);
    const unsigned long long ww7 = pk2(dw_w[c*9+7], dw_w[c*9+7]);
    const unsigned long long ww8 = pk2(dw_w[c*9+8], dw_w[c*9+8]);
    const float s = g1[c] * rsqrtf(v1[c] + EPSV);
    const float t = fmaf(dw_b[c] - m1[c], s, b1[c]);
    const unsigned long long ss = pk2(s, s);
    const unsigned long long tt = pk2(t, t);

    const int tid = threadIdx.x;

    {   // stage slice: 784 coalesced float4
        const float4* x4 = (const float4*)xs;
        float4* s4 = (float4*)sx;
        for (int i = tid; i < 784; i += 256) s4[i] = x4[i];
    }
    __syncthreads();

    float2 lv[7];
    float mx = 0.f;
    int p = 0, band = 0;
    if (tid < 224) {
        band = tid / 28;               // 0..7
        p    = tid - band * 28;        // col pair 0..27 -> cols 2p, 2p+1
        const bool cL = (p > 0), cR = (p < 27);
        const int col = 2 * p;
        const int r0  = band * 7;      // first output row of this thread

        // window rows r-1, r: packed pairs q0=(c-1,c) q1=(c,c+1) q2=(c+1,c+2)
        unsigned long long r0q0, r0q1, r0q2, r1q0, r1q1, r1q2;
        {
            float c0 = 0.f, c1 = 0.f, c2 = 0.f, c3 = 0.f;
            if (r0 > 0) {
                int a = (r0 - 1) * 56 + col;
                c0 = cL ? sx[a - 1] : 0.f;
                c1 = sx[a]; c2 = sx[a + 1];
                c3 = cR ? sx[a + 2] : 0.f;
            }
            r0q0 = pk2(c0, c1); r0q1 = pk2(c1, c2); r0q2 = pk2(c2, c3);
        }
        {
            int a = r0 * 56 + col;
            float c0 = cL ? sx[a - 1] : 0.f;
            float c1 = sx[a], c2 = sx[a + 1];
            float c3 = cR ? sx[a + 2] : 0.f;
            r1q0 = pk2(c0, c1); r1q1 = pk2(c1, c2); r1q2 = pk2(c2, c3);
        }

#pragma unroll
        for (int j = 0; j < 7; j++) {
            const int rr = r0 + j + 1;                 // row below
            unsigned long long r2q0, r2q1, r2q2;
            {
                float c0 = 0.f, c1 = 0.f, c2 = 0.f, c3 = 0.f;
                if (rr < 56) {
                    int a = rr * 56 + col;
                    c0 = cL ? sx[a - 1] : 0.f;
                    c1 = sx[a]; c2 = sx[a + 1];
                    c3 = cR ? sx[a + 2] : 0.f;
                }
                r2q0 = pk2(c0, c1); r2q1 = pk2(c1, c2); r2q2 = pk2(c2, c3);
            }
            // same per-lane FMA order as the scalar reference chain
            unsigned long long acc = mul2(r0q0, ww0);
            acc = fma2(r0q1, ww1, acc); acc = fma2(r0q2, ww2, acc);
            acc = fma2(r1q0, ww3, acc); acc = fma2(r1q1, ww4, acc);
            acc = fma2(r1q2, ww5, acc);
            acc = fma2(r2q0, ww6, acc); acc = fma2(r2q1, ww7, acc);
            acc = fma2(r2q2, ww8, acc);
            acc = fma2(acc, ss, tt);
            float2 pr = upk2(acc);
            float z0 = fmaxf(pr.x, 0.f), z1 = fmaxf(pr.y, 0.f);
            lv[j] = make_float2(z0, z1);
            mx = fmaxf(mx, fmaxf(z0, z1));
            r0q0 = r1q0; r0q1 = r1q1; r0q2 = r1q2;
            r1q0 = r2q0; r1q1 = r2q1; r1q2 = r2q2;
        }
    }

    for (int off = 16; off; off >>= 1)
        mx = fmaxf(mx, __shfl_xor_sync(0xffffffffu, mx, off));
    if ((tid & 31) == 0) red[tid >> 5] = mx;
    __syncthreads();
    if (tid == 0) {
        float m = red[0];
#pragma unroll
        for (int i = 1; i < 8; i++) m = fmaxf(m, red[i]);
        s_bmax = m;
        g_keep[slice] = (m >= DW_THR) ? 1 : 0;
    }
    __syncthreads();

    if (s_bmax >= DW_THR && tid < 224) {
        float* yo = g_y + (size_t)slice * 3136 + band * 7 * 56 + 2 * p;
#pragma unroll
        for (int j = 0; j < 7; j++)
            *(float2*)(yo + j * 56) = lv[j];
    }
}

// ---------------------------------------------------------------------------
// Per-batch compaction of kept channels + zero g_max (graph-replay safe)
// ---------------------------------------------------------------------------
__global__ void compact_kernel() {
    const int b = blockIdx.x;
    const int tid = threadIdx.x;              // 256 threads
    g_max[b * 256 + tid] = 0;
    __shared__ int wcnt[4];
    if (tid < 128) {
        const int f = g_keep[b * 128 + tid];
        const unsigned bal = __ballot_sync(0xffffffffu, f);
        const int lane = tid & 31, w = tid >> 5;
        const int pre = __popc(bal & ((1u << lane) - 1u));
        if (lane == 0) wcnt[w] = __popc(bal);
        __syncthreads();
        int off = 0;
#pragma unroll
        for (int i = 0; i < 4; i++) if (i < w) off += wcnt[i];
        if (f) g_idx[b * 128 + off + pre] = tid;
        if (tid == 0) g_cnt[b] = wcnt[0] + wcnt[1] + wcnt[2] + wcnt[3];
    } else {
        __syncthreads();
    }
}

// ---------------------------------------------------------------------------
// Pointwise GEMM over compacted K + BN2 + ReLU + per-(b,o) max.
// Tile 128(O) x 64(HW), 8x4 microtile, FFMA2, KT=16 (one tile when cnt<=16).
// grid = (49, 2, 64), 256 threads.
// ---------------------------------------------------------------------------
#define KT 16
__global__ __launch_bounds__(256, 4) void pw_kernel(
    const float* __restrict__ pw_w, const float* __restrict__ pw_b,
    const float* __restrict__ g2,  const float* __restrict__ b2,
    const float* __restrict__ m2,  const float* __restrict__ v2,
    float* __restrict__ out)
{
    __shared__ float sW[KT][132];   // [k][o]
    __shared__ float sY[KT][68];    // [k][hw]
    __shared__ int   sidx[KT];

    const int tid = threadIdx.x;
    const int tx = tid & 15;        // hw: 16 threads x 4
    const int ty = tid >> 4;        // o : 16 threads x 8
    const int hwb = blockIdx.x * 64;
    const int ob  = blockIdx.y * 128;
    const int b   = blockIdx.z;

    const int cnt = g_cnt[b];
    const int ntiles = (cnt + KT - 1) / KT;

    unsigned long long acc[4][4];
#pragma unroll
    for (int pp = 0; pp < 4; pp++)
#pragma unroll
        for (int q = 0; q < 4; q++) acc[pp][q] = 0ull;

    for (int kt = 0; kt < ntiles; kt++) {
        int klim = cnt - kt * KT;
        if (klim > KT) klim = KT;
        const int kstage = (klim + 3) & ~3;

        if (tid < KT) {
            int kk = kt * KT + tid;
            sidx[tid] = (kk < cnt) ? g_idx[b * 128 + kk] : -1;
        }
        __syncthreads();

        // W tile: gather+transpose -> sW[k][o], rows k < kstage
#pragma unroll
        for (int j = 0; j < 8; j++) {
            int idx = j * 256 + tid;        // 2048 = 16k x 128o
            int o = idx >> 4, k = idx & 15;
            if (k < kstage) {
                int ch = sidx[k];
                sW[k][o] = (ch >= 0) ? pw_w[(ob + o) * 128 + ch] : 0.f;
            }
        }
        // Y tile: 16k x 16 f4 = 256 threads
        {
            int k = tid >> 4, f4 = tid & 15;
            if (k < kstage) {
                int ch = sidx[k];
                float4 v = make_float4(0.f, 0.f, 0.f, 0.f);
                if (ch >= 0)
                    v = *(const float4*)(g_y + ((size_t)(b * 128 + ch)) * 3136 + hwb + f4 * 4);
                *(float4*)&sY[k][f4 * 4] = v;
            }
        }
        __syncthreads();

        for (int k0 = 0; k0 < klim; k0 += 4) {
#pragma unroll
            for (int ku = 0; ku < 4; ku++) {
                int k = k0 + ku;
                float4 A0 = *(const float4*)&sW[k][ty * 8];
                float4 A1 = *(const float4*)&sW[k][ty * 8 + 4];
                float4 B0 = *(const float4*)&sY[k][tx * 4];
                unsigned long long av[4];
                av[0] = pk2(A0.x, A0.y); av[1] = pk2(A0.z, A0.w);
                av[2] = pk2(A1.x, A1.y); av[3] = pk2(A1.z, A1.w);
                unsigned long long bq[4];
                bq[0] = pk2(B0.x, B0.x); bq[1] = pk2(B0.y, B0.y);
                bq[2] = pk2(B0.z, B0.z); bq[3] = pk2(B0.w, B0.w);
#pragma unroll
                for (int pp = 0; pp < 4; pp++)
#pragma unroll
                    for (int q = 0; q < 4; q++)
                        acc[pp][q] = fma2(av[pp], bq[q], acc[pp][q]);
            }
        }
        __syncthreads();
    }

    // epilogue: BN2 + ReLU + per-(b,o) max + store
#pragma unroll
    for (int r = 0; r < 8; r++) {
        int o = ob + ty * 8 + r;
        float sc = g2[o] * rsqrtf(v2[o] + EPSV);
        float tt = fmaf(pw_b[o] - m2[o], sc, b2[o]);
        float z[4];
        float m = 0.f;
#pragma unroll
        for (int q = 0; q < 4; q++) {
            float2 pr = upk2(acc[r >> 1][q]);
            float v = (r & 1) ? pr.y : pr.x;
            float zz = fmaxf(fmaf(v, sc, tt), 0.f);
            z[q] = zz;
            m = fmaxf(m, zz);
        }
#pragma unroll
        for (int off = 1; off < 16; off <<= 1)
            m = fmaxf(m, __shfl_xor_sync(0xffffffffu, m, off));
        if (tx == 0) atomicMax(&g_max[b * 256 + o], __float_as_int(m));
        float* po = out + ((size_t)(b * 256 + o)) * 3136 + hwb + tx * 4;
        *(float4*)po = make_float4(z[0], z[1], z[2], z[3]);
    }
}

// ---------------------------------------------------------------------------
// Final prune: one (b,o) slice per block; pass -> immediate exit (no sync).
// ---------------------------------------------------------------------------
__global__ __launch_bounds__(128) void prune_kernel(float* __restrict__ out) {
    const int slice = blockIdx.x;
    if (__int_as_float(g_max[slice]) >= PW_THR) return;   // warp-broadcast LDG
    const float4 zz = make_float4(0.f, 0.f, 0.f, 0.f);
    float4* p4 = (float4*)(out + (size_t)slice * 3136);
    const int tid = threadIdx.x;
#pragma unroll
    for (int j = 0; j < 6; j++) p4[tid + j * 128] = zz;   // 768
    if (tid < 16) p4[768 + tid] = zz;                      // 784
}

// ---------------------------------------------------------------------------
extern "C" void kernel_launch(void* const* d_in, const int* in_sizes, int n_in,
                              void* d_out, int out_size)
{
    const float* x    = (const float*)d_in[0];
    const float* dw_w = (const float*)d_in[1];
    const float* dw_b = (const float*)d_in[2];
    const float* g1   = (const float*)d_in[3];
    const float* b1   = (const float*)d_in[4];
    const float* m1   = (const float*)d_in[5];
    const float* v1   = (const float*)d_in[6];
    const float* pw_w = (const float*)d_in[7];
    const float* pw_b = (const float*)d_in[8];
    const float* g2   = (const float*)d_in[9];
    const float* b2   = (const float*)d_in[10];
    const float* m2   = (const float*)d_in[11];
    const float* v2   = (const float*)d_in[12];
    float* out = (float*)d_out;

    dw_kernel<<<64 * 128, 256>>>(x, dw_w, dw_b, g1, b1, m1, v1);
    compact_kernel<<<64, 256>>>();
    pw_kernel<<<dim3(49, 2, 64), 256>>>(pw_w, pw_b, g2, b2, m2, v2, out);
    prune_kernel<<<64 * 256, 128>>>(out);
}